// round 5
// baseline (speedup 1.0000x reference)
#include <cuda_runtime.h>
#include <cfloat>

// VQ nearest-codebook: z_e [32,64,64,64] f32 (B,C,H,W), embedding [1024,64] f32
// out = embedding[argmin_k ||z - e_k||^2] scattered back to [B,C,H,W].
//
// Pass 1 (fast, fp32x2 GEMM): approximate distances, track top-2 per point.
// Pass 2 (exact, fp64): re-rank the two candidates -> true argmin.

#define NPOINTS   131072
#define KCODES    1024
#define CDIM      64
#define CP        32          // channel pairs (f32x2)
#define MB        128         // points per block
#define NB        64          // codes per chunk
#define NCHUNK    (KCODES / NB)

__device__ float g_eSq[KCODES];

__global__ void esq_kernel(const float* __restrict__ emb) {
    int k = blockIdx.x * 256 + threadIdx.x;
    if (k < KCODES) {
        const float* r = emb + k * CDIM;
        float s = 0.f;
        #pragma unroll
        for (int c = 0; c < CDIM; c++) s = fmaf(r[c], r[c], s);
        g_eSq[k] = s;
    }
}

__device__ __forceinline__ float2 u2f(unsigned long long u) {
    float2 f;
    asm("mov.b64 {%0,%1}, %2;" : "=f"(f.x), "=f"(f.y) : "l"(u));
    return f;
}

__global__ __launch_bounds__(256) void vq_kernel(
    const float* __restrict__ z,
    const float* __restrict__ emb,
    float* __restrict__ out)
{
    // zsm: [chp][point] f32x2, 32*128*8 = 32768 B; reused as top-2 scratch later
    __shared__ __align__(16) unsigned long long zsm[CP * MB];
    // esm: [chp][code] f32x2 with pad (65) for conflict-free staging stores
    __shared__ __align__(16) unsigned long long esm[CP * 65];
    __shared__ int bidx[MB];

    const int tid = threadIdx.x;
    const int tp  = tid & 15;   // point group: points tp + 16*j, j=0..7
    const int tc  = tid >> 4;   // code  group: codes  tc + 16*k, k=0..3

    const int n0  = blockIdx.x * MB;
    const int b   = n0 >> 12;          // H*W = 4096, 128 | 4096 so b constant
    const int hw0 = n0 & 4095;
    const float* zb = z + (size_t)b * CDIM * 4096 + hw0;

    // ---- stage z tile transposed into channel-pair-packed smem ----
    {
        float* zsf = (float*)zsm;
        #pragma unroll
        for (int i = 0; i < 32; i++) {
            int idx = i * 256 + tid;
            int ch = idx >> 7, p = idx & 127;              // coalesced over p
            zsf[(ch >> 1) * 256 + p * 2 + (ch & 1)] = zb[ch * 4096 + p];
        }
    }

    float b1[8], b2[8];
    int   i1[8], i2[8];
    #pragma unroll
    for (int j = 0; j < 8; j++) {
        b1[j] = FLT_MAX; b2[j] = FLT_MAX; i1[j] = KCODES; i2[j] = KCODES;
    }

    unsigned long long acc[8][4];
    #pragma unroll
    for (int j = 0; j < 8; j++)
        #pragma unroll
        for (int k = 0; k < 4; k++) acc[j][k] = 0ULL;

    for (int cc = 0; cc < NCHUNK; cc++) {
        __syncthreads();   // esm safe to overwrite (also covers zsm on cc==0)
        // ---- stage 64-code chunk, gmem-coalesced over channel ----
        {
            float* esf = (float*)esm;
            const float* ebase = emb + cc * NB * CDIM;
            #pragma unroll
            for (int i = 0; i < 16; i++) {
                int idx = i * 256 + tid;
                int ch = idx & 63, c = idx >> 6;           // coalesced over ch
                esf[(ch >> 1) * 130 + c * 2 + (ch & 1)] = ebase[c * CDIM + ch];
            }
        }
        __syncthreads();

        // ---- main GEMM: 8 points x 4 codes per thread, f32x2 packed ----
        #pragma unroll 8
        for (int chp = 0; chp < CP; chp++) {
            const unsigned long long* zr = zsm + chp * MB + tp;
            const unsigned long long* er = esm + chp * 65 + tc;
            unsigned long long zp[8], ep[4];
            #pragma unroll
            for (int j = 0; j < 8; j++) zp[j] = zr[16 * j];
            #pragma unroll
            for (int k = 0; k < 4; k++) ep[k] = er[16 * k];
            #pragma unroll
            for (int j = 0; j < 8; j++)
                #pragma unroll
                for (int k = 0; k < 4; k++)
                    asm("fma.rn.f32x2 %0, %1, %2, %0;"
                        : "+l"(acc[j][k]) : "l"(zp[j]), "l"(ep[k]));
        }

        // ---- chunk epilogue: dist = ||e||^2 - 2*dot, running top-2 ----
        #pragma unroll
        for (int k = 0; k < 4; k++) {
            int c = cc * NB + tc + 16 * k;
            float esq = g_eSq[c];
            #pragma unroll
            for (int j = 0; j < 8; j++) {
                float2 a = u2f(acc[j][k]);
                acc[j][k] = 0ULL;
                float dist = fmaf(-2.0f, a.x + a.y, esq);
                if (dist < b1[j]) {
                    b2[j] = b1[j]; i2[j] = i1[j];
                    b1[j] = dist;  i1[j] = c;
                } else if (dist < b2[j]) {
                    b2[j] = dist;  i2[j] = c;
                }
            }
        }
    }

    // ---- cross-thread top-2 merge (16 tc-threads per point) ----
    __syncthreads();                       // all GEMM reads of zsm done
    float4* red = (float4*)zsm;            // [point][tc] = (d1, i1, d2, i2)
    #pragma unroll
    for (int j = 0; j < 8; j++) {
        int p = tp + 16 * j;
        red[p * 16 + tc] = make_float4(b1[j], __int_as_float(i1[j]),
                                       b2[j], __int_as_float(i2[j]));
    }
    __syncthreads();

    if (tid < MB) {
        float d1 = FLT_MAX, d2 = FLT_MAX;
        int   c1 = KCODES,  c2 = KCODES;
        #pragma unroll
        for (int t = 0; t < 16; t++) {
            float4 v = red[tid * 16 + t];
            float dv[2] = { v.x, v.z };
            int   iv[2] = { __float_as_int(v.y), __float_as_int(v.w) };
            #pragma unroll
            for (int u = 0; u < 2; u++) {
                float d = dv[u]; int i = iv[u];
                if (d < d1 || (d == d1 && i < c1)) {
                    d2 = d1; c2 = c1; d1 = d; c1 = i;
                } else if (d < d2 || (d == d2 && i < c2)) {
                    d2 = d; c2 = i;
                }
            }
        }
        // ---- exact fp64 re-rank of the two candidates ----
        int pick = c1;
        if (c2 < KCODES) {
            const float* e1 = emb + (size_t)c1 * CDIM;
            const float* e2 = emb + (size_t)c2 * CDIM;
            double s1 = 0.0, s2 = 0.0;
            #pragma unroll 8
            for (int ch = 0; ch < CDIM; ch++) {
                double zc = (double)zb[ch * 4096 + tid];   // coalesced over tid
                double q1 = zc - (double)e1[ch];
                double q2 = zc - (double)e2[ch];
                s1 = fma(q1, q1, s1);
                s2 = fma(q2, q2, s2);
            }
            if (s2 < s1 || (s2 == s1 && c2 < c1)) pick = c2;
        }
        bidx[tid] = pick;
    }
    __syncthreads();

    // ---- gather + scatter back to [B,C,H,W] (coalesced stores) ----
    #pragma unroll
    for (int i = 0; i < 32; i++) {
        int idx = i * 256 + tid;
        int ch = idx >> 7, p = idx & 127;
        out[(size_t)(b * CDIM + ch) * 4096 + hw0 + p] = emb[bidx[p] * CDIM + ch];
    }
}

extern "C" void kernel_launch(void* const* d_in, const int* in_sizes, int n_in,
                              void* d_out, int out_size) {
    const float* z   = (const float*)d_in[0];
    const float* emb = (const float*)d_in[1];
    float* out = (float*)d_out;
    esq_kernel<<<(KCODES + 255) / 256, 256>>>(emb);
    vq_kernel<<<NPOINTS / MB, 256>>>(z, emb, out);
}